// round 11
// baseline (speedup 1.0000x reference)
#include <cuda_runtime.h>
#include <cuda_fp16.h>
#include <math.h>
#include <stdint.h>

#define NN    8192
#define BB    16
#define CCH   128
#define MODES 64
#define KSPLIT 16

// ---------------- scratch ----------------
__device__ float  g_lutc[8192];                          // cos(2*pi*t/8192)
__device__ __half g_Th[128 * NN];                        // full basis fp16 [j][n] (for inverse)
__device__ __half g_Tc[128 * 4096];                      // folded basis [cls*64+jj][n<4096]
__device__ __half g_xh[(size_t)2048 * NN];               // x fp16 [r][n] (for inverse conv part)
__device__ __half g_xe[(size_t)2048 * 4096];             // x[n]+x[n+4096] fp16
__device__ __half g_xo[(size_t)2048 * 4096];             // x[n]-x[n+4096] fp16
__device__ __half g_Ah[BB * 128 * 256];                  // inv A fp16 [b][o][k]
__device__ float  g_Pt[(size_t)KSPLIT * BB * 128 * 128]; // fwd partials [ks][b][j][i]
__device__ float  g_wT[MODES * CCH * CCH * 2];           // [m][o][i][re,im]

// ---------------- helpers ----------------
__device__ __forceinline__ uint32_t smem_u32(const void* p) {
    uint32_t a;
    asm("{ .reg .u64 t; cvta.to.shared.u64 t, %1; cvt.u32.u64 %0, t; }" : "=r"(a) : "l"(p));
    return a;
}
#define LDSM4(R, addr) \
    asm volatile("ldmatrix.sync.aligned.m8n8.x4.shared.b16 {%0,%1,%2,%3}, [%4];" \
        : "=r"((R)[0]), "=r"((R)[1]), "=r"((R)[2]), "=r"((R)[3]) : "r"(addr))
#define LDSM4T(R, addr) \
    asm volatile("ldmatrix.sync.aligned.m8n8.x4.trans.shared.b16 {%0,%1,%2,%3}, [%4];" \
        : "=r"((R)[0]), "=r"((R)[1]), "=r"((R)[2]), "=r"((R)[3]) : "r"(addr))
#define CP16(dst, src) \
    asm volatile("cp.async.cg.shared.global [%0], [%1], 16;" :: "r"(dst), "l"(src))
#define CPCOMMIT() asm volatile("cp.async.commit_group;" ::: "memory")
#define CPWAIT0()  asm volatile("cp.async.wait_group 0;" ::: "memory")
#define CPWAIT1()  asm volatile("cp.async.wait_group 1;" ::: "memory")

__device__ __forceinline__ void mma16816(float* c, const uint32_t* a, uint32_t b0, uint32_t b1) {
    asm volatile("mma.sync.aligned.m16n8k16.row.col.f32.f16.f16.f32 "
        "{%0,%1,%2,%3}, {%4,%5,%6,%7}, {%8,%9}, {%0,%1,%2,%3};"
        : "+f"(c[0]), "+f"(c[1]), "+f"(c[2]), "+f"(c[3])
        : "r"(a[0]), "r"(a[1]), "r"(a[2]), "r"(a[3]), "r"(b0), "r"(b1));
}
__device__ __forceinline__ uint32_t packh(__half a, __half b) {
    return (uint32_t)__half_as_ushort(a) | ((uint32_t)__half_as_ushort(b) << 16);
}
__device__ __forceinline__ uint2 cvt4(float4 v) {
    return make_uint2(packh(__float2half(v.x), __float2half(v.y)),
                      packh(__float2half(v.z), __float2half(v.w)));
}

// fwd stage: A [256 rows(xe||xo)][64 k] p144 @0 (36864B); B [128 rows(Te||To)][64 k] p144 @36864 (18432B)
#define FB_OFF 36864
#define FSZ    55296
#define FSMEM  (2 * FSZ)
// inv: A static [128 o][256 k] p528 @0 (67584B); B 2 stages [64 k][128 n] p272 @67584 (17408B each)
#define IB_OFF 67584
#define IBSZ   17408
#define ISMEM  (IB_OFF + 2 * IBSZ)

// ---------------------------------------------------------------------------
// Prep
// ---------------------------------------------------------------------------
__global__ void lut_fill() {
    int t = blockIdx.x * 256 + threadIdx.x;   // 8192
    float s, c;
    sincospif((float)t * (1.0f / 4096.0f), &s, &c);
    g_lutc[t] = c;
}

__global__ void fill_T() {
    int idx = blockIdx.x * 256 + threadIdx.x;   // 128*8192
    int j = idx >> 13;
    int n = idx & (NN - 1);
    int m = j & 63;
    int t = (m * n) & (NN - 1);
    if (j >= MODES) t = (t + 6144) & (NN - 1);   // sin = cos shifted
    g_Th[idx] = __float2half(g_lutc[t]);
}

__global__ void fill_Tc() {
    int idx = blockIdx.x * 256 + threadIdx.x;   // 128*4096
    int row = idx >> 12;
    int n = idx & 4095;
    int cls = row >> 6, jj = row & 63;
    int m = 2 * (jj & 31) + cls;
    int t = (m * n) & (NN - 1);
    if (jj >= 32) t = (t + 6144) & (NN - 1);     // sin rows
    g_Tc[idx] = __float2half(g_lutc[t]);
}

__global__ void transpose_w(const float* __restrict__ w_spec) {
    int idx = blockIdx.x * 256 + threadIdx.x;   // 64*128*32
    int m  = idx & 63;
    int o  = (idx >> 6) & 127;
    int ib = idx >> 13;
    float2 v[4];
#pragma unroll
    for (int q = 0; q < 4; q++) {
        int i = ib * 4 + q;
        v[q] = *(const float2*)(w_spec + ((size_t)(i * CCH + o) * MODES + m) * 2);
    }
    float* dst = g_wT + ((size_t)(m * CCH + o) * CCH + ib * 4) * 2;
    *(float4*)(dst)     = make_float4(v[0].x, v[0].y, v[1].x, v[1].y);
    *(float4*)(dst + 4) = make_float4(v[2].x, v[2].y, v[3].x, v[3].y);
}

__global__ void prep_wc(const float* __restrict__ w_conv) {
    int idx = blockIdx.x * 256 + threadIdx.x;   // 16*128*128
    int b = idx >> 14;
    int o = (idx >> 7) & 127;
    int i = idx & 127;
    g_Ah[((size_t)(b * 128 + o)) * 256 + 128 + i] = __float2half(w_conv[o * 128 + i]);
}

// fold + convert: xh (both halves), xe = lo+hi, xo = lo-hi
__global__ void prep_split(const float* __restrict__ x) {
    int idx = blockIdx.x * 256 + threadIdx.x;     // 2048*1024
    int r = idx >> 10, c4 = idx & 1023;
    const float4* xr = (const float4*)x + (size_t)r * 2048;
    float4 a = xr[c4];
    float4 b = xr[c4 + 1024];
    ((uint2*)g_xh)[(size_t)r * 2048 + c4]        = cvt4(a);
    ((uint2*)g_xh)[(size_t)r * 2048 + 1024 + c4] = cvt4(b);
    float4 e = make_float4(a.x + b.x, a.y + b.y, a.z + b.z, a.w + b.w);
    float4 o = make_float4(a.x - b.x, a.y - b.y, a.z - b.z, a.w - b.w);
    ((uint2*)g_xe)[(size_t)r * 1024 + c4] = cvt4(e);
    ((uint2*)g_xo)[(size_t)r * 1024 + c4] = cvt4(o);
}

// ---------------------------------------------------------------------------
// fwd compute: one (128 i)x(128 j)x(64 folded k) tile.
// A region has xe rows 0..127, xo rows 128..255; wn selects class.
// ---------------------------------------------------------------------------
__device__ __forceinline__ void compute_tile_f(float acc[2][8][4], uint32_t stg,
                                               int wm, int wn, int lane) {
    uint32_t n_off = (lane & 7) + ((lane >> 4) << 3);
    uint32_t kb = ((lane >> 3) & 1) * 16;
    uint32_t abase = stg + (uint32_t)(wn * 128 + wm * 32 + (lane & 15)) * 144 + (lane >> 4) * 16;
    uint32_t bbase = stg + FB_OFF + (uint32_t)(wn * 64 + n_off) * 144 + kb;
#pragma unroll
    for (int s16 = 0; s16 < 4; s16++) {
        uint32_t ah[2][4];
        LDSM4(ah[0], abase + s16 * 32);
        LDSM4(ah[1], abase + s16 * 32 + 16 * 144);
#pragma unroll
        for (int nb = 0; nb < 4; nb++) {
            uint32_t bh[4];
            LDSM4(bh, bbase + s16 * 32 + nb * 16 * 144);
#pragma unroll
            for (int half = 0; half < 2; half++) {
                int n = nb * 2 + half;
#pragma unroll
                for (int m = 0; m < 2; m++)
                    mma16816(acc[m][n], ah[m], bh[half * 2], bh[half * 2 + 1]);
            }
        }
    }
}

// inv compute: A static region p528 (k-tile kt), B via ldmatrix.trans p272
__device__ __forceinline__ void compute_tile_i(float acc[2][8][4], uint32_t sb,
                                               uint32_t bst, int kt,
                                               int wm, int wn, int lane) {
    uint32_t abase = sb + (uint32_t)(wm * 32 + (lane & 15)) * 528 + kt * 128 + (lane >> 4) * 16;
    uint32_t bbase = bst + (uint32_t)(lane & 15) * 272 + (uint32_t)(wn * 64) * 2 + (lane >> 4) * 16;
#pragma unroll
    for (int s16 = 0; s16 < 4; s16++) {
        uint32_t ah[2][4];
        LDSM4(ah[0], abase + s16 * 32);
        LDSM4(ah[1], abase + s16 * 32 + 16 * 528);
        uint32_t brow = bbase + (uint32_t)(s16 * 16) * 272;
#pragma unroll
        for (int nb = 0; nb < 4; nb++) {
            uint32_t bh[4];
            LDSM4T(bh, brow + nb * 32);
#pragma unroll
            for (int m = 0; m < 2; m++) {
                mma16816(acc[m][nb * 2],     ah[m], bh[0], bh[1]);
                mma16816(acc[m][nb * 2 + 1], ah[m], bh[2], bh[3]);
            }
        }
    }
}

// ---------------------------------------------------------------------------
// Forward GEMM (folded): Pt[ks][b][j][i] = sum_{folded k in chunk} xc[i][k]*Tc[j][k]
// grid (BB, KSPLIT), 256 threads, 2 CTAs/SM; chunk = 256 folded k = 4 k64-tiles
// ---------------------------------------------------------------------------
__global__ __launch_bounds__(256, 2) void gemm_fwd_mma() {
    extern __shared__ char smem[];
    uint32_t sb = smem_u32(smem);
    int t = threadIdx.x, lane = t & 31, wid = t >> 5;
    int wm = wid & 3, wn = wid >> 2;
    int b = blockIdx.x, ks = blockIdx.y;
    int r0 = b * 128, kbase = ks * 256;
    const int NT = 4;

    float acc[2][8][4];
#pragma unroll
    for (int m = 0; m < 2; m++)
#pragma unroll
        for (int n = 0; n < 8; n++)
#pragma unroll
            for (int e = 0; e < 4; e++) acc[m][n][e] = 0.f;

#define FWD_ISSUE(T) do { \
    int _k0 = kbase + (T) * 64; \
    uint32_t _st = sb + ((T) & 1) * FSZ; \
    _Pragma("unroll") \
    for (int q = 0; q < 8; q++) { \
        int c = t + q * 256, ar = c >> 3, u = c & 7; \
        const __half* asrc = ((ar & 128) ? g_xo : g_xe) \
                           + (size_t)(r0 + (ar & 127)) * 4096 + _k0 + u * 8; \
        CP16(_st + ar * 144 + u * 16, asrc); \
    } \
    _Pragma("unroll") \
    for (int q = 0; q < 4; q++) { \
        int c = t + q * 256, row = c >> 3, u = c & 7; \
        CP16(_st + FB_OFF + row * 144 + u * 16, g_Tc + (size_t)row * 4096 + _k0 + u * 8); \
    } \
    CPCOMMIT(); \
} while (0)

    FWD_ISSUE(0);
    FWD_ISSUE(1);
#pragma unroll
    for (int tile = 0; tile < NT; tile++) {
        if (tile + 1 < NT) { CPWAIT1(); } else { CPWAIT0(); }
        __syncthreads();
        compute_tile_f(acc, sb + (tile & 1) * FSZ, wm, wn, lane);
        __syncthreads();                 // 2-stage: next issue targets this buffer
        if (tile + 2 < NT) FWD_ISSUE(tile + 2);
    }

    // epilogue: scatter to global-j rows through SMEM, then linear copy-out
    float* ftile = (float*)smem;   // [128 j][132]
#pragma unroll
    for (int m = 0; m < 2; m++) {
        int i = wm * 32 + m * 16 + (lane >> 2);
#pragma unroll
        for (int n = 0; n < 8; n++) {
            int jj = n * 8 + (lane & 3) * 2;    // local (even) col within class
            int jg = (jj < 32) ? (2 * jj + wn) : (64 + 2 * (jj - 32) + wn);
            ftile[jg * 132 + i]             = acc[m][n][0];
            ftile[(jg + 2) * 132 + i]       = acc[m][n][1];
            ftile[jg * 132 + i + 8]         = acc[m][n][2];
            ftile[(jg + 2) * 132 + i + 8]   = acc[m][n][3];
        }
    }
    __syncthreads();
    float* P = g_Pt + ((size_t)(ks * BB + b)) * 128 * 128;
#pragma unroll
    for (int w = 0; w < 16; w++) {
        int idx4 = t + w * 256;
        int j = idx4 >> 5, i4 = idx4 & 31;
        *(float4*)(P + (size_t)j * 128 + i4 * 4) = *(const float4*)&ftile[j * 132 + i4 * 4];
    }
}

// ---------------------------------------------------------------------------
// Mode mix (folds split-K reduce) -> fp16 coefficients into g_Ah [b][o][k<128]
// ---------------------------------------------------------------------------
__global__ __launch_bounds__(256) void mode_mix() {
    int m = blockIdx.x, bg = blockIdx.y;
    int t = threadIdx.x;
    __shared__ float Fre[4][128], Fim[4][128];
#pragma unroll
    for (int q = 0; q < 2; q++) {
        int flat = t + q * 256;
        int bq = flat >> 7, i = flat & 127;
        int b = bg * 4 + bq;
        float sr = 0.f, si = 0.f;
#pragma unroll
        for (int ks = 0; ks < KSPLIT; ks++) {
            const float* Pb = g_Pt + ((size_t)(ks * BB + b)) * 128 * 128;
            sr += Pb[(size_t)m * 128 + i];
            si += Pb[(size_t)(64 + m) * 128 + i];
        }
        Fre[bq][i] = sr;
        Fim[bq][i] = -si;
    }
    __syncthreads();
    int o = t & 127, half = t >> 7;
    float aR[2] = {0.f, 0.f}, aI[2] = {0.f, 0.f};
    const float2* wrow = (const float2*)g_wT + (size_t)(m * CCH + o) * CCH;
#pragma unroll 8
    for (int i = 0; i < CCH; i++) {
        float2 w = wrow[i];
#pragma unroll
        for (int p = 0; p < 2; p++) {
            int bq = half * 2 + p;
            float fr = Fre[bq][i], fi = Fim[bq][i];
            aR[p] = fmaf(fr, w.x, fmaf(-fi, w.y, aR[p]));
            aI[p] = fmaf(fr, w.y, fmaf( fi, w.x, aI[p]));
        }
    }
    float sR = (m == 0) ? (1.0f / (float)NN) : (2.0f / (float)NN);
    float sI = (m == 0) ? 0.0f : (-2.0f / (float)NN);
#pragma unroll
    for (int p = 0; p < 2; p++) {
        int b = bg * 4 + half * 2 + p;
        size_t base = ((size_t)(b * 128 + o)) * 256;
        g_Ah[base + m]      = __float2half(aR[p] * sR);
        g_Ah[base + 64 + m] = __float2half(aI[p] * sI);
    }
}

// ---------------------------------------------------------------------------
// Inverse GEMM (fused iDFT + conv1x1 + bias + exact GELU)
// A loaded once per CTA (p528), 2 n-tiles per CTA, B 2-stage cp.async.
// grid (32 nt-pairs, 16 b)
// ---------------------------------------------------------------------------
__global__ __launch_bounds__(256, 2) void gemm_inv_mma(const float* __restrict__ b_conv,
                                                       float* __restrict__ out) {
    extern __shared__ char smem[];
    uint32_t sb = smem_u32(smem);
    int t = threadIdx.x, lane = t & 31, wid = t >> 5;
    int wm = wid & 3, wn = wid >> 2;
    int ntp = blockIdx.x, b = blockIdx.y;

    const __half* Ahb = g_Ah + (size_t)b * 32768;

#define IB_LOAD(TT) do { \
    int _nt2 = (TT) >> 2, _kt = (TT) & 3; \
    int _n0 = (ntp * 2 + _nt2) * 128; \
    int _k0 = _kt * 64; \
    uint32_t _st = sb + IB_OFF + ((TT) & 1) * IBSZ; \
    _Pragma("unroll") \
    for (int q = 0; q < 4; q++) { \
        int c = t + q * 256, kr = c >> 4, cc = c & 15; \
        int _k = _k0 + kr; \
        const __half* src = (_k < 128) ? (g_Th + (size_t)_k * NN + _n0) \
                                       : (g_xh + (size_t)(b * 128 + _k - 128) * NN + _n0); \
        CP16(_st + kr * 272 + cc * 16, src + cc * 8); \
    } \
    CPCOMMIT(); \
} while (0)

    // prologue: A (once) + B(0) in group 0; B(1) in group 1
    {
#pragma unroll
        for (int q = 0; q < 16; q++) {
            int c = t + q * 256, row = c >> 5, u = c & 31;
            CP16(sb + row * 528 + u * 16, Ahb + (size_t)row * 256 + u * 8);
        }
        IB_LOAD(0);   // commits group 0 (A + B0)
        IB_LOAD(1);   // group 1
    }

    float acc[2][8][4];
#pragma unroll
    for (int m = 0; m < 2; m++)
#pragma unroll
        for (int n = 0; n < 8; n++)
#pragma unroll
            for (int e = 0; e < 4; e++) acc[m][n][e] = 0.f;

#pragma unroll
    for (int tt = 0; tt < 8; tt++) {
        int nt2 = tt >> 2, kt = tt & 3;
        if (tt + 1 < 8) { CPWAIT1(); } else { CPWAIT0(); }
        __syncthreads();
        compute_tile_i(acc, sb, sb + IB_OFF + (tt & 1) * IBSZ, kt, wm, wn, lane);
        __syncthreads();                 // 2-stage: next issue targets this buffer
        if (tt + 2 < 8) IB_LOAD(tt + 2);

        if (kt == 3) {
            // epilogue for this n-tile: bias + exact GELU + store, then reset acc
            int n0 = (ntp * 2 + nt2) * 128;
#pragma unroll
            for (int m = 0; m < 2; m++) {
                int o0 = wm * 32 + m * 16 + (lane >> 2);
                float bias0 = b_conv[o0];
                float bias1 = b_conv[o0 + 8];
#pragma unroll
                for (int n = 0; n < 8; n++) {
                    int ng = n0 + wn * 64 + n * 8 + (lane & 3) * 2;
                    float v0 = acc[m][n][0] + bias0;
                    float v1 = acc[m][n][1] + bias0;
                    float v2 = acc[m][n][2] + bias1;
                    float v3 = acc[m][n][3] + bias1;
                    v0 = 0.5f * v0 * (1.0f + erff(v0 * 0.70710678118654752f));
                    v1 = 0.5f * v1 * (1.0f + erff(v1 * 0.70710678118654752f));
                    v2 = 0.5f * v2 * (1.0f + erff(v2 * 0.70710678118654752f));
                    v3 = 0.5f * v3 * (1.0f + erff(v3 * 0.70710678118654752f));
                    *(float2*)(out + ((size_t)(b * 128 + o0)) * NN + ng)     = make_float2(v0, v1);
                    *(float2*)(out + ((size_t)(b * 128 + o0 + 8)) * NN + ng) = make_float2(v2, v3);
                }
            }
#pragma unroll
            for (int m = 0; m < 2; m++)
#pragma unroll
                for (int n = 0; n < 8; n++)
#pragma unroll
                    for (int e = 0; e < 4; e++) acc[m][n][e] = 0.f;
        }
    }
}

// ---------------------------------------------------------------------------
extern "C" void kernel_launch(void* const* d_in, const int* in_sizes, int n_in,
                              void* d_out, int out_size) {
    const float* x      = (const float*)d_in[0];
    const float* w_spec = (const float*)d_in[1];
    const float* w_conv = (const float*)d_in[2];
    const float* b_conv = (const float*)d_in[3];
    float* out = (float*)d_out;

    cudaFuncSetAttribute(gemm_fwd_mma, cudaFuncAttributeMaxDynamicSharedMemorySize, FSMEM);
    cudaFuncSetAttribute(gemm_inv_mma, cudaFuncAttributeMaxDynamicSharedMemorySize, ISMEM);

    lut_fill   <<<32, 256>>>();
    fill_T     <<<(128 * NN) / 256, 256>>>();
    fill_Tc    <<<(128 * 4096) / 256, 256>>>();
    transpose_w<<<(MODES * CCH * 32) / 256, 256>>>(w_spec);
    prep_wc    <<<(BB * 128 * 128) / 256, 256>>>(w_conv);
    prep_split <<<(2048 * 1024) / 256, 256>>>(x);

    gemm_fwd_mma<<<dim3(BB, KSPLIT), 256, FSMEM>>>();
    mode_mix    <<<dim3(MODES, 4), 256>>>();
    gemm_inv_mma<<<dim3(NN / 256, BB), 256, ISMEM>>>(b_conv, out);
}

// round 12
// speedup vs baseline: 1.0580x; 1.0580x over previous
#include <cuda_runtime.h>
#include <cuda_fp16.h>
#include <math.h>
#include <stdint.h>

#define NN    8192
#define BB    16
#define CCH   128
#define MODES 64
#define KSPLIT 16

// ---------------- scratch ----------------
__device__ float  g_lutc[8192];                          // cos(2*pi*t/8192)
__device__ __half g_Th[128 * NN];                        // basis fp16 [j][n]
__device__ __half g_xh[(size_t)2048 * NN];               // x fp16 [r][n]
__device__ __half g_Ah[BB * 128 * 128];                  // inv A coeffs fp16 [b][o][k<128]
__device__ __half g_wc[128 * 128];                       // w_conv fp16 [o][i]
__device__ float  g_Pt[(size_t)KSPLIT * BB * 128 * 128]; // fwd partials [ks][b][j][i]
__device__ float  g_wT[MODES * CCH * CCH * 2];           // [m][o][i][re,im]

// ---------------- helpers ----------------
__device__ __forceinline__ uint32_t smem_u32(const void* p) {
    uint32_t a;
    asm("{ .reg .u64 t; cvta.to.shared.u64 t, %1; cvt.u32.u64 %0, t; }" : "=r"(a) : "l"(p));
    return a;
}
#define LDSM4(R, addr) \
    asm volatile("ldmatrix.sync.aligned.m8n8.x4.shared.b16 {%0,%1,%2,%3}, [%4];" \
        : "=r"((R)[0]), "=r"((R)[1]), "=r"((R)[2]), "=r"((R)[3]) : "r"(addr))
#define LDSM4T(R, addr) \
    asm volatile("ldmatrix.sync.aligned.m8n8.x4.trans.shared.b16 {%0,%1,%2,%3}, [%4];" \
        : "=r"((R)[0]), "=r"((R)[1]), "=r"((R)[2]), "=r"((R)[3]) : "r"(addr))
#define CP16(dst, src) \
    asm volatile("cp.async.cg.shared.global [%0], [%1], 16;" :: "r"(dst), "l"(src))
#define CPCOMMIT() asm volatile("cp.async.commit_group;" ::: "memory")
#define CPWAIT0()  asm volatile("cp.async.wait_group 0;" ::: "memory")
#define CPWAIT1()  asm volatile("cp.async.wait_group 1;" ::: "memory")

__device__ __forceinline__ void mma16816(float* c, const uint32_t* a, uint32_t b0, uint32_t b1) {
    asm volatile("mma.sync.aligned.m16n8k16.row.col.f32.f16.f16.f32 "
        "{%0,%1,%2,%3}, {%4,%5,%6,%7}, {%8,%9}, {%0,%1,%2,%3};"
        : "+f"(c[0]), "+f"(c[1]), "+f"(c[2]), "+f"(c[3])
        : "r"(a[0]), "r"(a[1]), "r"(a[2]), "r"(a[3]), "r"(b0), "r"(b1));
}
__device__ __forceinline__ uint32_t packh(__half a, __half b) {
    return (uint32_t)__half_as_ushort(a) | ((uint32_t)__half_as_ushort(b) << 16);
}
__device__ __forceinline__ uint2 cvt4(float4 v) {
    return make_uint2(packh(__float2half(v.x), __float2half(v.y)),
                      packh(__float2half(v.z), __float2half(v.w)));
}

// stage layouts (k-tile = 64, pitch 144 = 128+16)
// fwd: A [128 r][64 k] @0 ; B [128 j][64 k] @18432
#define FB_OFF 18432
#define FSZ    36864
#define FSMEM  (3 * FSZ)
// inv: A [128 o][64 k] @0 p144 ; B [64 k][128 n] @18432 p272
#define IB_OFF 18432
#define ISZ    36864
#define ISMEM  (3 * ISZ)

// ---------------------------------------------------------------------------
// Prep
// ---------------------------------------------------------------------------
__global__ void lut_fill() {
    int t = blockIdx.x * 256 + threadIdx.x;   // 8192
    float s, c;
    sincospif((float)t * (1.0f / 4096.0f), &s, &c);
    g_lutc[t] = c;
}

// vectorized: each thread emits 8 halves (one uint4)
__global__ void fill_T() {
    int idx = blockIdx.x * 256 + threadIdx.x;   // 131072
    int base = idx * 8;
    int j = base >> 13;
    int n0 = base & (NN - 1);
    int m = j & 63;
    int phase = (j >= MODES) ? 6144 : 0;        // sin = cos shifted
    uint32_t h[4];
#pragma unroll
    for (int q = 0; q < 4; q++) {
        int t0 = (m * (n0 + 2 * q) + phase) & (NN - 1);
        int t1 = (m * (n0 + 2 * q + 1) + phase) & (NN - 1);
        h[q] = packh(__float2half(g_lutc[t0]), __float2half(g_lutc[t1]));
    }
    *(uint4*)(g_Th + base) = make_uint4(h[0], h[1], h[2], h[3]);
}

// coalesced both sides via smem tile: w_spec [i][o][m][2] -> g_wT [m][o][i][2]
__global__ __launch_bounds__(256) void transpose_w(const float* __restrict__ w_spec) {
    __shared__ float2 tile[64][33];       // [m][i-local]
    int o = blockIdx.x;        // 0..127
    int i0 = blockIdx.y * 32;  // 0..96
    int t = threadIdx.x;
    const float4* src4 = (const float4*)w_spec;
#pragma unroll
    for (int q = 0; q < 4; q++) {
        int idx = t + q * 256;
        int m4 = idx & 31;       // m-pair
        int i  = idx >> 5;       // 0..31
        float4 v = src4[((size_t)(i0 + i) * 128 + o) * 32 + m4];
        tile[2 * m4][i]     = make_float2(v.x, v.y);
        tile[2 * m4 + 1][i] = make_float2(v.z, v.w);
    }
    __syncthreads();
    float4* dst4 = (float4*)g_wT;
#pragma unroll
    for (int q = 0; q < 4; q++) {
        int idx = t + q * 256;
        int il = idx & 15;       // i-pair
        int m  = idx >> 4;       // 0..63
        float2 a = tile[m][il * 2], b = tile[m][il * 2 + 1];
        dst4[((size_t)m * 128 + o) * 64 + (i0 >> 1) + il] = make_float4(a.x, a.y, b.x, b.y);
    }
}

__global__ void prep_wc(const float* __restrict__ w_conv) {
    int idx = blockIdx.x * 256 + threadIdx.x;   // 16384
    g_wc[idx] = __float2half(w_conv[idx]);
}

__global__ void prep_split(const float* __restrict__ x) {
    int idx4 = blockIdx.x * 256 + threadIdx.x;     // 4.19M float4
    float4 v = ((const float4*)x)[idx4];
    ((uint2*)g_xh)[idx4] = cvt4(v);
}

// ---------------------------------------------------------------------------
// fwd compute: one 128x128x64 tile, single-pass fp16
// ---------------------------------------------------------------------------
__device__ __forceinline__ void compute_tile_f(float acc[2][8][4], uint32_t stg,
                                               int wm, int wn, int lane) {
    uint32_t n_off = (lane & 7) + ((lane >> 4) << 3);
    uint32_t kb = ((lane >> 3) & 1) * 16;
#pragma unroll
    for (int s16 = 0; s16 < 4; s16++) {
        uint32_t ah[2][4];
        uint32_t aaddr = stg + (uint32_t)(wm * 32 + (lane & 15)) * 144
                       + s16 * 32 + (lane >> 4) * 16;
        LDSM4(ah[0], aaddr);
        LDSM4(ah[1], aaddr + 16 * 144);
        uint32_t baddr = stg + FB_OFF + (uint32_t)(wn * 64 + n_off) * 144 + s16 * 32 + kb;
#pragma unroll
        for (int nb = 0; nb < 4; nb++) {
            uint32_t bh[4];
            LDSM4(bh, baddr + nb * 16 * 144);
#pragma unroll
            for (int half = 0; half < 2; half++) {
                int n = nb * 2 + half;
#pragma unroll
                for (int m = 0; m < 2; m++)
                    mma16816(acc[m][n], ah[m], bh[half * 2], bh[half * 2 + 1]);
            }
        }
    }
}

// inv compute: B via ldmatrix.trans on [k][n] layout (pitch 272)
__device__ __forceinline__ void compute_tile_i(float acc[2][8][4], uint32_t stg,
                                               int wm, int wn, int lane) {
#pragma unroll
    for (int s16 = 0; s16 < 4; s16++) {
        uint32_t ah[2][4];
        uint32_t aaddr = stg + (uint32_t)(wm * 32 + (lane & 15)) * 144
                       + s16 * 32 + (lane >> 4) * 16;
        LDSM4(ah[0], aaddr);
        LDSM4(ah[1], aaddr + 16 * 144);
        uint32_t baddr = stg + IB_OFF + (uint32_t)(s16 * 16 + (lane & 15)) * 272
                       + (uint32_t)(wn * 64) * 2 + (lane >> 4) * 16;
#pragma unroll
        for (int nb = 0; nb < 4; nb++) {
            uint32_t bh[4];
            LDSM4T(bh, baddr + nb * 32);
#pragma unroll
            for (int m = 0; m < 2; m++) {
                mma16816(acc[m][nb * 2],     ah[m], bh[0], bh[1]);
                mma16816(acc[m][nb * 2 + 1], ah[m], bh[2], bh[3]);
            }
        }
    }
}

// ---------------------------------------------------------------------------
// Forward GEMM: Pt[ks][b][j][i] = sum_k xh[b*128+i][k] * T[j][k]
// grid (BB, KSPLIT), 256 threads, 2 CTAs/SM; K-chunk 512 = 8 k64-tiles
// ---------------------------------------------------------------------------
__global__ __launch_bounds__(256, 2) void gemm_fwd_mma() {
    extern __shared__ char smem[];
    uint32_t sb = smem_u32(smem);
    int t = threadIdx.x, lane = t & 31, wid = t >> 5;
    int wm = wid & 3, wn = wid >> 2;
    int b = blockIdx.x, ks = blockIdx.y;
    int r0 = b * 128, kbase = ks * (NN / KSPLIT);
    const int NT = (NN / KSPLIT) / 64;   // 8

    float acc[2][8][4];
#pragma unroll
    for (int m = 0; m < 2; m++)
#pragma unroll
        for (int n = 0; n < 8; n++)
#pragma unroll
            for (int e = 0; e < 4; e++) acc[m][n][e] = 0.f;

#define FWD_ISSUE(T) do { \
    int _k0 = kbase + (T) * 64; \
    uint32_t _st = sb + ((T) % 3) * FSZ; \
    _Pragma("unroll") \
    for (int q = 0; q < 4; q++) { \
        int c = t + q * 256, row = c >> 3, u = c & 7; \
        CP16(_st + row * 144 + u * 16, g_xh + (size_t)(r0 + row) * NN + _k0 + u * 8); \
        CP16(_st + FB_OFF + row * 144 + u * 16, g_Th + (size_t)row * NN + _k0 + u * 8); \
    } \
    CPCOMMIT(); \
} while (0)

    FWD_ISSUE(0);
    FWD_ISSUE(1);
#pragma unroll
    for (int tile = 0; tile < NT; tile++) {
        if (tile + 1 < NT) { CPWAIT1(); } else { CPWAIT0(); }
        __syncthreads();
        compute_tile_f(acc, sb + (tile % 3) * FSZ, wm, wn, lane);
        if (tile + 2 < NT) FWD_ISSUE(tile + 2);
    }
    __syncthreads();

    // epilogue: transpose through SMEM -> g_Pt[ks][b][j][i]
    float* ftile = (float*)smem;   // [j][132]
#pragma unroll
    for (int m = 0; m < 2; m++) {
        int r1 = wm * 32 + m * 16 + (lane >> 2);
#pragma unroll
        for (int n = 0; n < 8; n++) {
            int j = wn * 64 + n * 8 + (lane & 3) * 2;
            ftile[j * 132 + r1]           = acc[m][n][0];
            ftile[(j + 1) * 132 + r1]     = acc[m][n][1];
            ftile[j * 132 + r1 + 8]       = acc[m][n][2];
            ftile[(j + 1) * 132 + r1 + 8] = acc[m][n][3];
        }
    }
    __syncthreads();
    float* P = g_Pt + ((size_t)(ks * BB + b)) * 128 * 128;
#pragma unroll
    for (int w = 0; w < 16; w++) {
        int idx4 = t + w * 256;
        int j = idx4 >> 5, i4 = idx4 & 31;
        *(float4*)(P + (size_t)j * 128 + i4 * 4) = *(const float4*)&ftile[j * 132 + i4 * 4];
    }
}

// ---------------------------------------------------------------------------
// Mode mix (folds split-K reduce) -> fp16 coefficients into g_Ah [b][o][k<128]
// ---------------------------------------------------------------------------
__global__ __launch_bounds__(256) void mode_mix() {
    int m = blockIdx.x, bg = blockIdx.y;
    int t = threadIdx.x;
    __shared__ float Fre[4][128], Fim[4][128];
#pragma unroll
    for (int q = 0; q < 2; q++) {
        int flat = t + q * 256;
        int bq = flat >> 7, i = flat & 127;
        int b = bg * 4 + bq;
        float sr = 0.f, si = 0.f;
#pragma unroll
        for (int ks = 0; ks < KSPLIT; ks++) {
            const float* Pb = g_Pt + ((size_t)(ks * BB + b)) * 128 * 128;
            sr += Pb[(size_t)m * 128 + i];
            si += Pb[(size_t)(64 + m) * 128 + i];
        }
        Fre[bq][i] = sr;
        Fim[bq][i] = -si;
    }
    __syncthreads();
    int o = t & 127, half = t >> 7;   // half handles batches half*2, half*2+1
    float aR[2] = {0.f, 0.f}, aI[2] = {0.f, 0.f};
    const float2* wrow = (const float2*)g_wT + (size_t)(m * CCH + o) * CCH;
#pragma unroll 8
    for (int i = 0; i < CCH; i++) {
        float2 w = wrow[i];
#pragma unroll
        for (int p = 0; p < 2; p++) {
            int bq = half * 2 + p;
            float fr = Fre[bq][i], fi = Fim[bq][i];
            aR[p] = fmaf(fr, w.x, fmaf(-fi, w.y, aR[p]));
            aI[p] = fmaf(fr, w.y, fmaf( fi, w.x, aI[p]));
        }
    }
    float sR = (m == 0) ? (1.0f / (float)NN) : (2.0f / (float)NN);
    float sI = (m == 0) ? 0.0f : (-2.0f / (float)NN);
#pragma unroll
    for (int p = 0; p < 2; p++) {
        int b = bg * 4 + half * 2 + p;
        size_t base = ((size_t)(b * 128 + o)) * 128;
        g_Ah[base + m]      = __float2half(aR[p] * sR);
        g_Ah[base + 64 + m] = __float2half(aI[p] * sI);
    }
}

// ---------------------------------------------------------------------------
// Inverse GEMM (fused iDFT + conv1x1 + bias + exact GELU)
// D[o][n] = sum_k A[o][k]*B[k][n], K=256 = 4 k64-tiles. grid (64 nt, 16 b)
// A k<128: per-batch coeffs g_Ah; k>=128: shared w_conv table g_wc.
// ---------------------------------------------------------------------------
__global__ __launch_bounds__(256, 2) void gemm_inv_mma(const float* __restrict__ b_conv,
                                                       float* __restrict__ out) {
    extern __shared__ char smem[];
    uint32_t sb = smem_u32(smem);
    int t = threadIdx.x, lane = t & 31, wid = t >> 5;
    int wm = wid & 3, wn = wid >> 2;
    int nt = blockIdx.x, b = blockIdx.y;
    int n0 = nt * 128;
    const int NT = 4;

    const __half* Ahb = g_Ah + (size_t)b * 16384;

    float acc[2][8][4];
#pragma unroll
    for (int m = 0; m < 2; m++)
#pragma unroll
        for (int n = 0; n < 8; n++)
#pragma unroll
            for (int e = 0; e < 4; e++) acc[m][n][e] = 0.f;

#define INV_ISSUE(T) do { \
    int _k0 = (T) * 64; \
    uint32_t _st = sb + ((T) % 3) * ISZ; \
    const __half* _Asrc = (_k0 < 128) ? (Ahb + _k0) : (g_wc + (_k0 - 128)); \
    _Pragma("unroll") \
    for (int q = 0; q < 4; q++) { \
        int c = t + q * 256, row = c >> 3, u = c & 7; \
        CP16(_st + row * 144 + u * 16, _Asrc + (size_t)row * 128 + u * 8); \
    } \
    _Pragma("unroll") \
    for (int q = 0; q < 4; q++) { \
        int c = t + q * 256, kr = c >> 4, cc = c & 15; \
        int _k = _k0 + kr; \
        const __half* src = (_k < 128) ? (g_Th + (size_t)_k * NN + n0) \
                                       : (g_xh + (size_t)(b * 128 + _k - 128) * NN + n0); \
        CP16(_st + IB_OFF + kr * 272 + cc * 16, src + cc * 8); \
    } \
    CPCOMMIT(); \
} while (0)

    INV_ISSUE(0);
    INV_ISSUE(1);
#pragma unroll
    for (int tile = 0; tile < NT; tile++) {
        if (tile + 1 < NT) { CPWAIT1(); } else { CPWAIT0(); }
        __syncthreads();
        compute_tile_i(acc, sb + (tile % 3) * ISZ, wm, wn, lane);
        if (tile + 2 < NT) INV_ISSUE(tile + 2);
    }

    // epilogue: bias + exact GELU + store
#pragma unroll
    for (int m = 0; m < 2; m++) {
        int o0 = wm * 32 + m * 16 + (lane >> 2);
        float bias0 = b_conv[o0];
        float bias1 = b_conv[o0 + 8];
#pragma unroll
        for (int n = 0; n < 8; n++) {
            int ng = n0 + wn * 64 + n * 8 + (lane & 3) * 2;
            float v0 = acc[m][n][0] + bias0;
            float v1 = acc[m][n][1] + bias0;
            float v2 = acc[m][n][2] + bias1;
            float v3 = acc[m][n][3] + bias1;
            v0 = 0.5f * v0 * (1.0f + erff(v0 * 0.70710678118654752f));
            v1 = 0.5f * v1 * (1.0f + erff(v1 * 0.70710678118654752f));
            v2 = 0.5f * v2 * (1.0f + erff(v2 * 0.70710678118654752f));
            v3 = 0.5f * v3 * (1.0f + erff(v3 * 0.70710678118654752f));
            *(float2*)(out + ((size_t)(b * 128 + o0)) * NN + ng)     = make_float2(v0, v1);
            *(float2*)(out + ((size_t)(b * 128 + o0 + 8)) * NN + ng) = make_float2(v2, v3);
        }
    }
}

// ---------------------------------------------------------------------------
extern "C" void kernel_launch(void* const* d_in, const int* in_sizes, int n_in,
                              void* d_out, int out_size) {
    const float* x      = (const float*)d_in[0];
    const float* w_spec = (const float*)d_in[1];
    const float* w_conv = (const float*)d_in[2];
    const float* b_conv = (const float*)d_in[3];
    float* out = (float*)d_out;

    cudaFuncSetAttribute(gemm_fwd_mma, cudaFuncAttributeMaxDynamicSharedMemorySize, FSMEM);
    cudaFuncSetAttribute(gemm_inv_mma, cudaFuncAttributeMaxDynamicSharedMemorySize, ISMEM);

    lut_fill   <<<32, 256>>>();
    fill_T     <<<(128 * NN / 8) / 256, 256>>>();
    transpose_w<<<dim3(128, 4), 256>>>(w_spec);
    prep_wc    <<<(128 * 128) / 256, 256>>>(w_conv);
    prep_split <<<(2048 * NN / 4) / 256, 256>>>(x);

    gemm_fwd_mma<<<dim3(BB, KSPLIT), 256, FSMEM>>>();
    mode_mix    <<<dim3(MODES, 4), 256>>>();
    gemm_inv_mma<<<dim3(NN / 128, BB), 256, ISMEM>>>(b_conv, out);
}

// round 13
// speedup vs baseline: 1.1612x; 1.0976x over previous
#include <cuda_runtime.h>
#include <cuda_fp16.h>
#include <math.h>
#include <stdint.h>

#define NN    8192
#define BB    16
#define CCH   128
#define MODES 64
#define KSPLIT 16

// ---------------- scratch ----------------
__device__ __half g_Th[128 * NN];                        // basis fp16 [j][n]
__device__ __half g_xh[(size_t)2048 * NN];               // x fp16 [r][n]
__device__ __half g_Ah[BB * 128 * 128];                  // inv A coeffs fp16 [b][o][k<128]
__device__ __half g_wc[128 * 128];                       // w_conv fp16 [o][i]
__device__ float  g_Pt[(size_t)KSPLIT * BB * 128 * 128]; // fwd partials [ks][b][j][i]
__device__ float  g_wT[MODES * CCH * CCH * 2];           // [m][o][i][re,im]

// ---------------- helpers ----------------
__device__ __forceinline__ uint32_t smem_u32(const void* p) {
    uint32_t a;
    asm("{ .reg .u64 t; cvta.to.shared.u64 t, %1; cvt.u32.u64 %0, t; }" : "=r"(a) : "l"(p));
    return a;
}
#define LDSM4(R, addr) \
    asm volatile("ldmatrix.sync.aligned.m8n8.x4.shared.b16 {%0,%1,%2,%3}, [%4];" \
        : "=r"((R)[0]), "=r"((R)[1]), "=r"((R)[2]), "=r"((R)[3]) : "r"(addr))
#define LDSM4T(R, addr) \
    asm volatile("ldmatrix.sync.aligned.m8n8.x4.trans.shared.b16 {%0,%1,%2,%3}, [%4];" \
        : "=r"((R)[0]), "=r"((R)[1]), "=r"((R)[2]), "=r"((R)[3]) : "r"(addr))
#define CP16(dst, src) \
    asm volatile("cp.async.cg.shared.global [%0], [%1], 16;" :: "r"(dst), "l"(src))
#define CPCOMMIT() asm volatile("cp.async.commit_group;" ::: "memory")
#define CPWAIT0()  asm volatile("cp.async.wait_group 0;" ::: "memory")
#define CPWAIT1()  asm volatile("cp.async.wait_group 1;" ::: "memory")

__device__ __forceinline__ void mma16816(float* c, const uint32_t* a, uint32_t b0, uint32_t b1) {
    asm volatile("mma.sync.aligned.m16n8k16.row.col.f32.f16.f16.f32 "
        "{%0,%1,%2,%3}, {%4,%5,%6,%7}, {%8,%9}, {%0,%1,%2,%3};"
        : "+f"(c[0]), "+f"(c[1]), "+f"(c[2]), "+f"(c[3])
        : "r"(a[0]), "r"(a[1]), "r"(a[2]), "r"(a[3]), "r"(b0), "r"(b1));
}
__device__ __forceinline__ uint32_t packh(__half a, __half b) {
    return (uint32_t)__half_as_ushort(a) | ((uint32_t)__half_as_ushort(b) << 16);
}
__device__ __forceinline__ uint2 cvt4(float4 v) {
    return make_uint2(packh(__float2half(v.x), __float2half(v.y)),
                      packh(__float2half(v.z), __float2half(v.w)));
}

// stage layouts (k-tile = 64, pitch 144 = 128+16)
#define FB_OFF 18432
#define FSZ    36864
#define FSMEM  (3 * FSZ)
#define IB_OFF 18432
#define ISZ    36864
#define ISMEM  (3 * ISZ)

// fused-prep grid ranges
#define PREP_SPLIT_BLKS 16384
#define FILLT_BLKS      512
#define TRW_BLKS        512
#define WC_BLKS         64
#define PREP_BLKS (PREP_SPLIT_BLKS + FILLT_BLKS + TRW_BLKS + WC_BLKS)

// ---------------------------------------------------------------------------
// Fused prep: one launch does x->fp16, basis table, w transpose, w_conv cvt
// ---------------------------------------------------------------------------
__global__ __launch_bounds__(256) void prep_all(const float* __restrict__ x,
                                                const float* __restrict__ w_spec,
                                                const float* __restrict__ w_conv) {
    __shared__ float2 tile[64][33];
    int bid = blockIdx.x;
    int t = threadIdx.x;

    if (bid < PREP_SPLIT_BLKS) {
        // ---- x fp32 -> fp16 ----
        int idx4 = bid * 256 + t;
        float4 v = ((const float4*)x)[idx4];
        ((uint2*)g_xh)[idx4] = cvt4(v);
        return;
    }
    bid -= PREP_SPLIT_BLKS;
    if (bid < FILLT_BLKS) {
        // ---- basis table, 8 halves per thread, direct cospif ----
        int idx = bid * 256 + t;
        int base = idx * 8;
        int j = base >> 13;
        int n0 = base & (NN - 1);
        int m = j & 63;
        int phase = (j >= MODES) ? 6144 : 0;   // sin = cos shifted
        uint32_t h[4];
#pragma unroll
        for (int q = 0; q < 4; q++) {
            int t0 = (m * (n0 + 2 * q) + phase) & (NN - 1);
            int t1 = (m * (n0 + 2 * q + 1) + phase) & (NN - 1);
            float c0 = cospif((float)t0 * (1.0f / 4096.0f));
            float c1 = cospif((float)t1 * (1.0f / 4096.0f));
            h[q] = packh(__float2half(c0), __float2half(c1));
        }
        *(uint4*)(g_Th + base) = make_uint4(h[0], h[1], h[2], h[3]);
        return;
    }
    bid -= FILLT_BLKS;
    if (bid < TRW_BLKS) {
        // ---- w_spec [i][o][m][2] -> g_wT [m][o][i][2] via smem tile ----
        int o = bid & 127;
        int i0 = (bid >> 7) * 32;
        const float4* src4 = (const float4*)w_spec;
#pragma unroll
        for (int q = 0; q < 4; q++) {
            int idx = t + q * 256;
            int m4 = idx & 31;
            int i  = idx >> 5;
            float4 v = src4[((size_t)(i0 + i) * 128 + o) * 32 + m4];
            tile[2 * m4][i]     = make_float2(v.x, v.y);
            tile[2 * m4 + 1][i] = make_float2(v.z, v.w);
        }
        __syncthreads();
        float4* dst4 = (float4*)g_wT;
#pragma unroll
        for (int q = 0; q < 4; q++) {
            int idx = t + q * 256;
            int il = idx & 15;
            int m  = idx >> 4;
            float2 a = tile[m][il * 2], b = tile[m][il * 2 + 1];
            dst4[((size_t)m * 128 + o) * 64 + (i0 >> 1) + il] = make_float4(a.x, a.y, b.x, b.y);
        }
        return;
    }
    bid -= TRW_BLKS;
    {
        // ---- w_conv fp32 -> fp16 ----
        int idx = bid * 256 + t;
        g_wc[idx] = __float2half(w_conv[idx]);
    }
}

// ---------------------------------------------------------------------------
// fwd compute: one 128x128x64 tile, single-pass fp16
// ---------------------------------------------------------------------------
__device__ __forceinline__ void compute_tile_f(float acc[2][8][4], uint32_t stg,
                                               int wm, int wn, int lane) {
    uint32_t n_off = (lane & 7) + ((lane >> 4) << 3);
    uint32_t kb = ((lane >> 3) & 1) * 16;
#pragma unroll
    for (int s16 = 0; s16 < 4; s16++) {
        uint32_t ah[2][4];
        uint32_t aaddr = stg + (uint32_t)(wm * 32 + (lane & 15)) * 144
                       + s16 * 32 + (lane >> 4) * 16;
        LDSM4(ah[0], aaddr);
        LDSM4(ah[1], aaddr + 16 * 144);
        uint32_t baddr = stg + FB_OFF + (uint32_t)(wn * 64 + n_off) * 144 + s16 * 32 + kb;
#pragma unroll
        for (int nb = 0; nb < 4; nb++) {
            uint32_t bh[4];
            LDSM4(bh, baddr + nb * 16 * 144);
#pragma unroll
            for (int half = 0; half < 2; half++) {
                int n = nb * 2 + half;
#pragma unroll
                for (int m = 0; m < 2; m++)
                    mma16816(acc[m][n], ah[m], bh[half * 2], bh[half * 2 + 1]);
            }
        }
    }
}

// inv compute: B via ldmatrix.trans on [k][n] layout (pitch 272)
__device__ __forceinline__ void compute_tile_i(float acc[2][8][4], uint32_t stg,
                                               int wm, int wn, int lane) {
#pragma unroll
    for (int s16 = 0; s16 < 4; s16++) {
        uint32_t ah[2][4];
        uint32_t aaddr = stg + (uint32_t)(wm * 32 + (lane & 15)) * 144
                       + s16 * 32 + (lane >> 4) * 16;
        LDSM4(ah[0], aaddr);
        LDSM4(ah[1], aaddr + 16 * 144);
        uint32_t baddr = stg + IB_OFF + (uint32_t)(s16 * 16 + (lane & 15)) * 272
                       + (uint32_t)(wn * 64) * 2 + (lane >> 4) * 16;
#pragma unroll
        for (int nb = 0; nb < 4; nb++) {
            uint32_t bh[4];
            LDSM4T(bh, baddr + nb * 32);
#pragma unroll
            for (int m = 0; m < 2; m++) {
                mma16816(acc[m][nb * 2],     ah[m], bh[0], bh[1]);
                mma16816(acc[m][nb * 2 + 1], ah[m], bh[2], bh[3]);
            }
        }
    }
}

// ---------------------------------------------------------------------------
// Forward GEMM: Pt[ks][b][j][i] = sum_k xh[b*128+i][k] * T[j][k]
// grid (BB, KSPLIT), 256 threads, 2 CTAs/SM; K-chunk 512 = 8 k64-tiles
// ---------------------------------------------------------------------------
__global__ __launch_bounds__(256, 2) void gemm_fwd_mma() {
    extern __shared__ char smem[];
    uint32_t sb = smem_u32(smem);
    int t = threadIdx.x, lane = t & 31, wid = t >> 5;
    int wm = wid & 3, wn = wid >> 2;
    int b = blockIdx.x, ks = blockIdx.y;
    int r0 = b * 128, kbase = ks * (NN / KSPLIT);
    const int NT = (NN / KSPLIT) / 64;   // 8

    float acc[2][8][4];
#pragma unroll
    for (int m = 0; m < 2; m++)
#pragma unroll
        for (int n = 0; n < 8; n++)
#pragma unroll
            for (int e = 0; e < 4; e++) acc[m][n][e] = 0.f;

#define FWD_ISSUE(T) do { \
    int _k0 = kbase + (T) * 64; \
    uint32_t _st = sb + ((T) % 3) * FSZ; \
    _Pragma("unroll") \
    for (int q = 0; q < 4; q++) { \
        int c = t + q * 256, row = c >> 3, u = c & 7; \
        CP16(_st + row * 144 + u * 16, g_xh + (size_t)(r0 + row) * NN + _k0 + u * 8); \
        CP16(_st + FB_OFF + row * 144 + u * 16, g_Th + (size_t)row * NN + _k0 + u * 8); \
    } \
    CPCOMMIT(); \
} while (0)

    FWD_ISSUE(0);
    FWD_ISSUE(1);
#pragma unroll
    for (int tile = 0; tile < NT; tile++) {
        if (tile + 1 < NT) { CPWAIT1(); } else { CPWAIT0(); }
        __syncthreads();
        compute_tile_f(acc, sb + (tile % 3) * FSZ, wm, wn, lane);
        if (tile + 2 < NT) FWD_ISSUE(tile + 2);
    }
    __syncthreads();

    // epilogue: transpose through SMEM -> g_Pt[ks][b][j][i]
    float* ftile = (float*)smem;   // [j][132]
#pragma unroll
    for (int m = 0; m < 2; m++) {
        int r1 = wm * 32 + m * 16 + (lane >> 2);
#pragma unroll
        for (int n = 0; n < 8; n++) {
            int j = wn * 64 + n * 8 + (lane & 3) * 2;
            ftile[j * 132 + r1]           = acc[m][n][0];
            ftile[(j + 1) * 132 + r1]     = acc[m][n][1];
            ftile[j * 132 + r1 + 8]       = acc[m][n][2];
            ftile[(j + 1) * 132 + r1 + 8] = acc[m][n][3];
        }
    }
    __syncthreads();
    float* P = g_Pt + ((size_t)(ks * BB + b)) * 128 * 128;
#pragma unroll
    for (int w = 0; w < 16; w++) {
        int idx4 = t + w * 256;
        int j = idx4 >> 5, i4 = idx4 & 31;
        *(float4*)(P + (size_t)j * 128 + i4 * 4) = *(const float4*)&ftile[j * 132 + i4 * 4];
    }
}

// ---------------------------------------------------------------------------
// Mode mix (folds split-K reduce) -> fp16 coefficients into g_Ah [b][o][k<128]
// ---------------------------------------------------------------------------
__global__ __launch_bounds__(256) void mode_mix() {
    int m = blockIdx.x, bg = blockIdx.y;
    int t = threadIdx.x;
    __shared__ float Fre[4][128], Fim[4][128];
#pragma unroll
    for (int q = 0; q < 2; q++) {
        int flat = t + q * 256;
        int bq = flat >> 7, i = flat & 127;
        int b = bg * 4 + bq;
        float sr = 0.f, si = 0.f;
#pragma unroll
        for (int ks = 0; ks < KSPLIT; ks++) {
            const float* Pb = g_Pt + ((size_t)(ks * BB + b)) * 128 * 128;
            sr += Pb[(size_t)m * 128 + i];
            si += Pb[(size_t)(64 + m) * 128 + i];
        }
        Fre[bq][i] = sr;
        Fim[bq][i] = -si;
    }
    __syncthreads();
    int o = t & 127, half = t >> 7;   // half handles batches half*2, half*2+1
    float aR[2] = {0.f, 0.f}, aI[2] = {0.f, 0.f};
    const float2* wrow = (const float2*)g_wT + (size_t)(m * CCH + o) * CCH;
#pragma unroll 8
    for (int i = 0; i < CCH; i++) {
        float2 w = wrow[i];
#pragma unroll
        for (int p = 0; p < 2; p++) {
            int bq = half * 2 + p;
            float fr = Fre[bq][i], fi = Fim[bq][i];
            aR[p] = fmaf(fr, w.x, fmaf(-fi, w.y, aR[p]));
            aI[p] = fmaf(fr, w.y, fmaf( fi, w.x, aI[p]));
        }
    }
    float sR = (m == 0) ? (1.0f / (float)NN) : (2.0f / (float)NN);
    float sI = (m == 0) ? 0.0f : (-2.0f / (float)NN);
#pragma unroll
    for (int p = 0; p < 2; p++) {
        int b = bg * 4 + half * 2 + p;
        size_t base = ((size_t)(b * 128 + o)) * 128;
        g_Ah[base + m]      = __float2half(aR[p] * sR);
        g_Ah[base + 64 + m] = __float2half(aI[p] * sI);
    }
}

// ---------------------------------------------------------------------------
// Inverse GEMM (fused iDFT + conv1x1 + bias + exact GELU)
// D[o][n] = sum_k A[o][k]*B[k][n], K=256 = 4 k64-tiles. grid (64 nt, 16 b)
// ---------------------------------------------------------------------------
__global__ __launch_bounds__(256, 2) void gemm_inv_mma(const float* __restrict__ b_conv,
                                                       float* __restrict__ out) {
    extern __shared__ char smem[];
    uint32_t sb = smem_u32(smem);
    int t = threadIdx.x, lane = t & 31, wid = t >> 5;
    int wm = wid & 3, wn = wid >> 2;
    int nt = blockIdx.x, b = blockIdx.y;
    int n0 = nt * 128;
    const int NT = 4;

    const __half* Ahb = g_Ah + (size_t)b * 16384;

    float acc[2][8][4];
#pragma unroll
    for (int m = 0; m < 2; m++)
#pragma unroll
        for (int n = 0; n < 8; n++)
#pragma unroll
            for (int e = 0; e < 4; e++) acc[m][n][e] = 0.f;

#define INV_ISSUE(T) do { \
    int _k0 = (T) * 64; \
    uint32_t _st = sb + ((T) % 3) * ISZ; \
    const __half* _Asrc = (_k0 < 128) ? (Ahb + _k0) : (g_wc + (_k0 - 128)); \
    _Pragma("unroll") \
    for (int q = 0; q < 4; q++) { \
        int c = t + q * 256, row = c >> 3, u = c & 7; \
        CP16(_st + row * 144 + u * 16, _Asrc + (size_t)row * 128 + u * 8); \
    } \
    _Pragma("unroll") \
    for (int q = 0; q < 4; q++) { \
        int c = t + q * 256, kr = c >> 4, cc = c & 15; \
        int _k = _k0 + kr; \
        const __half* src = (_k < 128) ? (g_Th + (size_t)_k * NN + n0) \
                                       : (g_xh + (size_t)(b * 128 + _k - 128) * NN + n0); \
        CP16(_st + IB_OFF + kr * 272 + cc * 16, src + cc * 8); \
    } \
    CPCOMMIT(); \
} while (0)

    INV_ISSUE(0);
    INV_ISSUE(1);
#pragma unroll
    for (int tile = 0; tile < NT; tile++) {
        if (tile + 1 < NT) { CPWAIT1(); } else { CPWAIT0(); }
        __syncthreads();
        compute_tile_i(acc, sb + (tile % 3) * ISZ, wm, wn, lane);
        if (tile + 2 < NT) INV_ISSUE(tile + 2);
    }

    // epilogue: bias + exact GELU + store
#pragma unroll
    for (int m = 0; m < 2; m++) {
        int o0 = wm * 32 + m * 16 + (lane >> 2);
        float bias0 = b_conv[o0];
        float bias1 = b_conv[o0 + 8];
#pragma unroll
        for (int n = 0; n < 8; n++) {
            int ng = n0 + wn * 64 + n * 8 + (lane & 3) * 2;
            float v0 = acc[m][n][0] + bias0;
            float v1 = acc[m][n][1] + bias0;
            float v2 = acc[m][n][2] + bias1;
            float v3 = acc[m][n][3] + bias1;
            v0 = 0.5f * v0 * (1.0f + erff(v0 * 0.70710678118654752f));
            v1 = 0.5f * v1 * (1.0f + erff(v1 * 0.70710678118654752f));
            v2 = 0.5f * v2 * (1.0f + erff(v2 * 0.70710678118654752f));
            v3 = 0.5f * v3 * (1.0f + erff(v3 * 0.70710678118654752f));
            *(float2*)(out + ((size_t)(b * 128 + o0)) * NN + ng)     = make_float2(v0, v1);
            *(float2*)(out + ((size_t)(b * 128 + o0 + 8)) * NN + ng) = make_float2(v2, v3);
        }
    }
}

// ---------------------------------------------------------------------------
extern "C" void kernel_launch(void* const* d_in, const int* in_sizes, int n_in,
                              void* d_out, int out_size) {
    const float* x      = (const float*)d_in[0];
    const float* w_spec = (const float*)d_in[1];
    const float* w_conv = (const float*)d_in[2];
    const float* b_conv = (const float*)d_in[3];
    float* out = (float*)d_out;

    cudaFuncSetAttribute(gemm_fwd_mma, cudaFuncAttributeMaxDynamicSharedMemorySize, FSMEM);
    cudaFuncSetAttribute(gemm_inv_mma, cudaFuncAttributeMaxDynamicSharedMemorySize, ISMEM);

    prep_all    <<<PREP_BLKS, 256>>>(x, w_spec, w_conv);
    gemm_fwd_mma<<<dim3(BB, KSPLIT), 256, FSMEM>>>();
    mode_mix    <<<dim3(MODES, 4), 256>>>();
    gemm_inv_mma<<<dim3(NN / 128, BB), 256, ISMEM>>>(b_conv, out);
}

// round 15
// speedup vs baseline: 1.2095x; 1.0416x over previous
#include <cuda_runtime.h>
#include <cuda_fp16.h>
#include <math.h>
#include <stdint.h>

#define NN    8192
#define BB    16
#define CCH   128
#define MODES 64
#define KSPLIT 16

// ---------------- scratch ----------------
__device__ __half g_Th[128 * NN];                        // basis fp16 [j][n]
__device__ __half g_xh[(size_t)2048 * NN];               // x fp16 [r][n]
__device__ __half g_Ah[BB * 128 * 128];                  // inv A coeffs fp16 [b][o][k<128]
__device__ __half g_wc[128 * 128];                       // w_conv fp16 [o][i]
__device__ float  g_Pt[(size_t)KSPLIT * BB * 128 * 128]; // fwd partials [ks][b][j][i]
__device__ float  g_wT[MODES * CCH * CCH * 2];           // [m][o][i][re,im]

// ---------------- helpers ----------------
__device__ __forceinline__ uint32_t smem_u32(const void* p) {
    uint32_t a;
    asm("{ .reg .u64 t; cvta.to.shared.u64 t, %1; cvt.u32.u64 %0, t; }" : "=r"(a) : "l"(p));
    return a;
}
#define LDSM4(R, addr) \
    asm volatile("ldmatrix.sync.aligned.m8n8.x4.shared.b16 {%0,%1,%2,%3}, [%4];" \
        : "=r"((R)[0]), "=r"((R)[1]), "=r"((R)[2]), "=r"((R)[3]) : "r"(addr))
#define LDSM4T(R, addr) \
    asm volatile("ldmatrix.sync.aligned.m8n8.x4.trans.shared.b16 {%0,%1,%2,%3}, [%4];" \
        : "=r"((R)[0]), "=r"((R)[1]), "=r"((R)[2]), "=r"((R)[3]) : "r"(addr))
#define CP16(dst, src) \
    asm volatile("cp.async.cg.shared.global [%0], [%1], 16;" :: "r"(dst), "l"(src))
#define CPCOMMIT() asm volatile("cp.async.commit_group;" ::: "memory")
#define CPWAIT0()  asm volatile("cp.async.wait_group 0;" ::: "memory")
#define CPWAIT1()  asm volatile("cp.async.wait_group 1;" ::: "memory")

__device__ __forceinline__ void mma16816(float* c, const uint32_t* a, uint32_t b0, uint32_t b1) {
    asm volatile("mma.sync.aligned.m16n8k16.row.col.f32.f16.f16.f32 "
        "{%0,%1,%2,%3}, {%4,%5,%6,%7}, {%8,%9}, {%0,%1,%2,%3};"
        : "+f"(c[0]), "+f"(c[1]), "+f"(c[2]), "+f"(c[3])
        : "r"(a[0]), "r"(a[1]), "r"(a[2]), "r"(a[3]), "r"(b0), "r"(b1));
}
__device__ __forceinline__ uint32_t packh(__half a, __half b) {
    return (uint32_t)__half_as_ushort(a) | ((uint32_t)__half_as_ushort(b) << 16);
}
__device__ __forceinline__ uint2 cvt4(float4 v) {
    return make_uint2(packh(__float2half(v.x), __float2half(v.y)),
                      packh(__float2half(v.z), __float2half(v.w)));
}
// fast GELU: tanh-form with hardware MUFU.TANH
__device__ __forceinline__ float gelu_fast(float v) {
    float u = v * v;
    float p = 0.79788456080286536f * v * fmaf(0.044715f, u, 1.0f);
    float t;
    asm("tanh.approx.f32 %0, %1;" : "=f"(t) : "f"(p));
    return 0.5f * v * (1.0f + t);
}

// stage layouts (k-tile = 64, pitch 144 = 128+16)
#define FB_OFF 18432
#define FSZ    36864
#define FSMEM  (3 * FSZ)
#define IB_OFF 18432
#define ISZ    36864
#define ISMEM  (3 * ISZ)

// fused-prep grid ranges
#define PREP_SPLIT_BLKS 16384
#define FILLT_BLKS      512
#define TRW_BLKS        512
#define WC_BLKS         64
#define PREP_BLKS (PREP_SPLIT_BLKS + FILLT_BLKS + TRW_BLKS + WC_BLKS)

// ---------------------------------------------------------------------------
// Fused prep: one launch does x->fp16, basis table, w transpose, w_conv cvt
// ---------------------------------------------------------------------------
__global__ __launch_bounds__(256) void prep_all(const float* __restrict__ x,
                                                const float* __restrict__ w_spec,
                                                const float* __restrict__ w_conv) {
    __shared__ float2 tile[64][33];
    int bid = blockIdx.x;
    int t = threadIdx.x;

    if (bid < PREP_SPLIT_BLKS) {
        // ---- x fp32 -> fp16 ----
        int idx4 = bid * 256 + t;
        float4 v = ((const float4*)x)[idx4];
        ((uint2*)g_xh)[idx4] = cvt4(v);
        return;
    }
    bid -= PREP_SPLIT_BLKS;
    if (bid < FILLT_BLKS) {
        // ---- basis table, 8 halves per thread, direct cospif ----
        int idx = bid * 256 + t;
        int base = idx * 8;
        int j = base >> 13;
        int n0 = base & (NN - 1);
        int m = j & 63;
        int phase = (j >= MODES) ? 6144 : 0;   // sin = cos shifted
        uint32_t h[4];
#pragma unroll
        for (int q = 0; q < 4; q++) {
            int t0 = (m * (n0 + 2 * q) + phase) & (NN - 1);
            int t1 = (m * (n0 + 2 * q + 1) + phase) & (NN - 1);
            float c0 = cospif((float)t0 * (1.0f / 4096.0f));
            float c1 = cospif((float)t1 * (1.0f / 4096.0f));
            h[q] = packh(__float2half(c0), __float2half(c1));
        }
        *(uint4*)(g_Th + base) = make_uint4(h[0], h[1], h[2], h[3]);
        return;
    }
    bid -= FILLT_BLKS;
    if (bid < TRW_BLKS) {
        // ---- w_spec [i][o][m][2] -> g_wT [m][o][i][2] via smem tile ----
        int o = bid & 127;
        int i0 = (bid >> 7) * 32;
        const float4* src4 = (const float4*)w_spec;
#pragma unroll
        for (int q = 0; q < 4; q++) {
            int idx = t + q * 256;
            int m4 = idx & 31;
            int i  = idx >> 5;
            float4 v = src4[((size_t)(i0 + i) * 128 + o) * 32 + m4];
            tile[2 * m4][i]     = make_float2(v.x, v.y);
            tile[2 * m4 + 1][i] = make_float2(v.z, v.w);
        }
        __syncthreads();
        float4* dst4 = (float4*)g_wT;
#pragma unroll
        for (int q = 0; q < 4; q++) {
            int idx = t + q * 256;
            int il = idx & 15;
            int m  = idx >> 4;
            float2 a = tile[m][il * 2], b = tile[m][il * 2 + 1];
            dst4[((size_t)m * 128 + o) * 64 + (i0 >> 1) + il] = make_float4(a.x, a.y, b.x, b.y);
        }
        return;
    }
    bid -= TRW_BLKS;
    {
        // ---- w_conv fp32 -> fp16 ----
        int idx = bid * 256 + t;
        g_wc[idx] = __float2half(w_conv[idx]);
    }
}

// ---------------------------------------------------------------------------
// fwd compute: one 128x128x64 tile, single-pass fp16
// ---------------------------------------------------------------------------
__device__ __forceinline__ void compute_tile_f(float acc[2][8][4], uint32_t stg,
                                               int wm, int wn, int lane) {
    uint32_t n_off = (lane & 7) + ((lane >> 4) << 3);
    uint32_t kb = ((lane >> 3) & 1) * 16;
#pragma unroll
    for (int s16 = 0; s16 < 4; s16++) {
        uint32_t ah[2][4];
        uint32_t aaddr = stg + (uint32_t)(wm * 32 + (lane & 15)) * 144
                       + s16 * 32 + (lane >> 4) * 16;
        LDSM4(ah[0], aaddr);
        LDSM4(ah[1], aaddr + 16 * 144);
        uint32_t baddr = stg + FB_OFF + (uint32_t)(wn * 64 + n_off) * 144 + s16 * 32 + kb;
#pragma unroll
        for (int nb = 0; nb < 4; nb++) {
            uint32_t bh[4];
            LDSM4(bh, baddr + nb * 16 * 144);
#pragma unroll
            for (int half = 0; half < 2; half++) {
                int n = nb * 2 + half;
#pragma unroll
                for (int m = 0; m < 2; m++)
                    mma16816(acc[m][n], ah[m], bh[half * 2], bh[half * 2 + 1]);
            }
        }
    }
}

// inv compute: B via ldmatrix.trans on [k][n] layout (pitch 272)
__device__ __forceinline__ void compute_tile_i(float acc[2][8][4], uint32_t stg,
                                               int wm, int wn, int lane) {
#pragma unroll
    for (int s16 = 0; s16 < 4; s16++) {
        uint32_t ah[2][4];
        uint32_t aaddr = stg + (uint32_t)(wm * 32 + (lane & 15)) * 144
                       + s16 * 32 + (lane >> 4) * 16;
        LDSM4(ah[0], aaddr);
        LDSM4(ah[1], aaddr + 16 * 144);
        uint32_t baddr = stg + IB_OFF + (uint32_t)(s16 * 16 + (lane & 15)) * 272
                       + (uint32_t)(wn * 64) * 2 + (lane >> 4) * 16;
#pragma unroll
        for (int nb = 0; nb < 4; nb++) {
            uint32_t bh[4];
            LDSM4T(bh, baddr + nb * 32);
#pragma unroll
            for (int m = 0; m < 2; m++) {
                mma16816(acc[m][nb * 2],     ah[m], bh[0], bh[1]);
                mma16816(acc[m][nb * 2 + 1], ah[m], bh[2], bh[3]);
            }
        }
    }
}

// ---------------------------------------------------------------------------
// Forward GEMM: Pt[ks][b][j][i] = sum_k xh[b*128+i][k] * T[j][k]
// grid (BB, KSPLIT), 256 threads, 2 CTAs/SM; K-chunk 512 = 8 k64-tiles
// ---------------------------------------------------------------------------
__global__ __launch_bounds__(256, 2) void gemm_fwd_mma() {
    extern __shared__ char smem[];
    uint32_t sb = smem_u32(smem);
    int t = threadIdx.x, lane = t & 31, wid = t >> 5;
    int wm = wid & 3, wn = wid >> 2;
    int b = blockIdx.x, ks = blockIdx.y;
    int r0 = b * 128, kbase = ks * (NN / KSPLIT);
    const int NT = (NN / KSPLIT) / 64;   // 8

    float acc[2][8][4];
#pragma unroll
    for (int m = 0; m < 2; m++)
#pragma unroll
        for (int n = 0; n < 8; n++)
#pragma unroll
            for (int e = 0; e < 4; e++) acc[m][n][e] = 0.f;

#define FWD_ISSUE(T) do { \
    int _k0 = kbase + (T) * 64; \
    uint32_t _st = sb + ((T) % 3) * FSZ; \
    _Pragma("unroll") \
    for (int q = 0; q < 4; q++) { \
        int c = t + q * 256, row = c >> 3, u = c & 7; \
        CP16(_st + row * 144 + u * 16, g_xh + (size_t)(r0 + row) * NN + _k0 + u * 8); \
        CP16(_st + FB_OFF + row * 144 + u * 16, g_Th + (size_t)row * NN + _k0 + u * 8); \
    } \
    CPCOMMIT(); \
} while (0)

    FWD_ISSUE(0);
    FWD_ISSUE(1);
#pragma unroll
    for (int tile = 0; tile < NT; tile++) {
        if (tile + 1 < NT) { CPWAIT1(); } else { CPWAIT0(); }
        __syncthreads();
        compute_tile_f(acc, sb + (tile % 3) * FSZ, wm, wn, lane);
        if (tile + 2 < NT) FWD_ISSUE(tile + 2);
    }
    __syncthreads();

    // epilogue: transpose through SMEM -> g_Pt[ks][b][j][i]
    float* ftile = (float*)smem;   // [j][132]
#pragma unroll
    for (int m = 0; m < 2; m++) {
        int r1 = wm * 32 + m * 16 + (lane >> 2);
#pragma unroll
        for (int n = 0; n < 8; n++) {
            int j = wn * 64 + n * 8 + (lane & 3) * 2;
            ftile[j * 132 + r1]           = acc[m][n][0];
            ftile[(j + 1) * 132 + r1]     = acc[m][n][1];
            ftile[j * 132 + r1 + 8]       = acc[m][n][2];
            ftile[(j + 1) * 132 + r1 + 8] = acc[m][n][3];
        }
    }
    __syncthreads();
    float* P = g_Pt + ((size_t)(ks * BB + b)) * 128 * 128;
#pragma unroll
    for (int w = 0; w < 16; w++) {
        int idx4 = t + w * 256;
        int j = idx4 >> 5, i4 = idx4 & 31;
        *(float4*)(P + (size_t)j * 128 + i4 * 4) = *(const float4*)&ftile[j * 132 + i4 * 4];
    }
}

// ---------------------------------------------------------------------------
// Mode mix (folds split-K reduce) -> fp16 coefficients into g_Ah [b][o][k<128]
// ---------------------------------------------------------------------------
__global__ __launch_bounds__(256) void mode_mix() {
    int m = blockIdx.x, bg = blockIdx.y;
    int t = threadIdx.x;
    __shared__ float Fre[4][128], Fim[4][128];
#pragma unroll
    for (int q = 0; q < 2; q++) {
        int flat = t + q * 256;
        int bq = flat >> 7, i = flat & 127;
        int b = bg * 4 + bq;
        float sr = 0.f, si = 0.f;
#pragma unroll
        for (int ks = 0; ks < KSPLIT; ks++) {
            const float* Pb = g_Pt + ((size_t)(ks * BB + b)) * 128 * 128;
            sr += Pb[(size_t)m * 128 + i];
            si += Pb[(size_t)(64 + m) * 128 + i];
        }
        Fre[bq][i] = sr;
        Fim[bq][i] = -si;
    }
    __syncthreads();
    int o = t & 127, half = t >> 7;   // half handles batches half*2, half*2+1
    float aR[2] = {0.f, 0.f}, aI[2] = {0.f, 0.f};
    const float2* wrow = (const float2*)g_wT + (size_t)(m * CCH + o) * CCH;
#pragma unroll 8
    for (int i = 0; i < CCH; i++) {
        float2 w = wrow[i];
#pragma unroll
        for (int p = 0; p < 2; p++) {
            int bq = half * 2 + p;
            float fr = Fre[bq][i], fi = Fim[bq][i];
            aR[p] = fmaf(fr, w.x, fmaf(-fi, w.y, aR[p]));
            aI[p] = fmaf(fr, w.y, fmaf( fi, w.x, aI[p]));
        }
    }
    float sR = (m == 0) ? (1.0f / (float)NN) : (2.0f / (float)NN);
    float sI = (m == 0) ? 0.0f : (-2.0f / (float)NN);
#pragma unroll
    for (int p = 0; p < 2; p++) {
        int b = bg * 4 + half * 2 + p;
        size_t base = ((size_t)(b * 128 + o)) * 128;
        g_Ah[base + m]      = __float2half(aR[p] * sR);
        g_Ah[base + 64 + m] = __float2half(aI[p] * sI);
    }
}

// ---------------------------------------------------------------------------
// Inverse GEMM (fused iDFT + conv1x1 + bias + fast GELU)
// D[o][n] = sum_k A[o][k]*B[k][n], K=256 = 4 k64-tiles. grid (64 nt, 16 b)
// ---------------------------------------------------------------------------
__global__ __launch_bounds__(256, 2) void gemm_inv_mma(const float* __restrict__ b_conv,
                                                       float* __restrict__ out) {
    extern __shared__ char smem[];
    uint32_t sb = smem_u32(smem);
    int t = threadIdx.x, lane = t & 31, wid = t >> 5;
    int wm = wid & 3, wn = wid >> 2;
    int nt = blockIdx.x, b = blockIdx.y;
    int n0 = nt * 128;
    const int NT = 4;

    const __half* Ahb = g_Ah + (size_t)b * 16384;

    float acc[2][8][4];
#pragma unroll
    for (int m = 0; m < 2; m++)
#pragma unroll
        for (int n = 0; n < 8; n++)
#pragma unroll
            for (int e = 0; e < 4; e++) acc[m][n][e] = 0.f;

#define INV_ISSUE(T) do { \
    int _k0 = (T) * 64; \
    uint32_t _st = sb + ((T) % 3) * ISZ; \
    const __half* _Asrc = (_k0 < 128) ? (Ahb + _k0) : (g_wc + (_k0 - 128)); \
    _Pragma("unroll") \
    for (int q = 0; q < 4; q++) { \
        int c = t + q * 256, row = c >> 3, u = c & 7; \
        CP16(_st + row * 144 + u * 16, _Asrc + (size_t)row * 128 + u * 8); \
    } \
    _Pragma("unroll") \
    for (int q = 0; q < 4; q++) { \
        int c = t + q * 256, kr = c >> 4, cc = c & 15; \
        int _k = _k0 + kr; \
        const __half* src = (_k < 128) ? (g_Th + (size_t)_k * NN + n0) \
                                       : (g_xh + (size_t)(b * 128 + _k - 128) * NN + n0); \
        CP16(_st + IB_OFF + kr * 272 + cc * 16, src + cc * 8); \
    } \
    CPCOMMIT(); \
} while (0)

    INV_ISSUE(0);
    INV_ISSUE(1);
#pragma unroll
    for (int tile = 0; tile < NT; tile++) {
        if (tile + 1 < NT) { CPWAIT1(); } else { CPWAIT0(); }
        __syncthreads();
        compute_tile_i(acc, sb + (tile % 3) * ISZ, wm, wn, lane);
        if (tile + 2 < NT) INV_ISSUE(tile + 2);
    }

    // epilogue: bias + fast GELU + store
#pragma unroll
    for (int m = 0; m < 2; m++) {
        int o0 = wm * 32 + m * 16 + (lane >> 2);
        float bias0 = b_conv[o0];
        float bias1 = b_conv[o0 + 8];
#pragma unroll
        for (int n = 0; n < 8; n++) {
            int ng = n0 + wn * 64 + n * 8 + (lane & 3) * 2;
            float v0 = gelu_fast(acc[m][n][0] + bias0);
            float v1 = gelu_fast(acc[m][n][1] + bias0);
            float v2 = gelu_fast(acc[m][n][2] + bias1);
            float v3 = gelu_fast(acc[m][n][3] + bias1);
            *(float2*)(out + ((size_t)(b * 128 + o0)) * NN + ng)     = make_float2(v0, v1);
            *(float2*)(out + ((size_t)(b * 128 + o0 + 8)) * NN + ng) = make_float2(v2, v3);
        }
    }
}

// ---------------------------------------------------------------------------
extern "C" void kernel_launch(void* const* d_in, const int* in_sizes, int n_in,
                              void* d_out, int out_size) {
    const float* x      = (const float*)d_in[0];
    const float* w_spec = (const float*)d_in[1];
    const float* w_conv = (const float*)d_in[2];
    const float* b_conv = (const float*)d_in[3];
    float* out = (float*)d_out;

    cudaFuncSetAttribute(gemm_fwd_mma, cudaFuncAttributeMaxDynamicSharedMemorySize, FSMEM);
    cudaFuncSetAttribute(gemm_inv_mma, cudaFuncAttributeMaxDynamicSharedMemorySize, ISMEM);

    prep_all    <<<PREP_BLKS, 256>>>(x, w_spec, w_conv);
    gemm_fwd_mma<<<dim3(BB, KSPLIT), 256, FSMEM>>>();
    mode_mix    <<<dim3(MODES, 4), 256>>>();
    gemm_inv_mma<<<dim3(NN / 128, BB), 256, ISMEM>>>(b_conv, out);
}

// round 16
// speedup vs baseline: 1.2099x; 1.0003x over previous
#include <cuda_runtime.h>
#include <cuda_fp16.h>
#include <math.h>
#include <stdint.h>

#define NN    8192
#define BB    16
#define CCH   128
#define MODES 64
#define KSPLIT 16

// ---------------- scratch ----------------
__device__ __half g_Th[128 * NN];                        // basis fp16 [j][n]
__device__ __half g_xh[(size_t)2048 * NN];               // x fp16 [r][n]
__device__ __half g_Ah[BB * 128 * 128];                  // inv A coeffs fp16 [b][o][k<128]
__device__ __half g_wc[128 * 128];                       // w_conv fp16 [o][i]
__device__ float  g_Pt[(size_t)KSPLIT * BB * 128 * 128]; // fwd partials [ks][b][j][i]
__device__ float  g_wT[MODES * CCH * CCH * 2];           // [m][o][i][re,im]

// ---------------- helpers ----------------
__device__ __forceinline__ uint32_t smem_u32(const void* p) {
    uint32_t a;
    asm("{ .reg .u64 t; cvta.to.shared.u64 t, %1; cvt.u32.u64 %0, t; }" : "=r"(a) : "l"(p));
    return a;
}
#define LDSM4(R, addr) \
    asm volatile("ldmatrix.sync.aligned.m8n8.x4.shared.b16 {%0,%1,%2,%3}, [%4];" \
        : "=r"((R)[0]), "=r"((R)[1]), "=r"((R)[2]), "=r"((R)[3]) : "r"(addr))
#define LDSM4T(R, addr) \
    asm volatile("ldmatrix.sync.aligned.m8n8.x4.trans.shared.b16 {%0,%1,%2,%3}, [%4];" \
        : "=r"((R)[0]), "=r"((R)[1]), "=r"((R)[2]), "=r"((R)[3]) : "r"(addr))
#define CP16(dst, src) \
    asm volatile("cp.async.cg.shared.global [%0], [%1], 16;" :: "r"(dst), "l"(src))
#define CPCOMMIT() asm volatile("cp.async.commit_group;" ::: "memory")
#define CPWAIT0()  asm volatile("cp.async.wait_group 0;" ::: "memory")
#define CPWAIT1()  asm volatile("cp.async.wait_group 1;" ::: "memory")

__device__ __forceinline__ void mma16816(float* c, const uint32_t* a, uint32_t b0, uint32_t b1) {
    asm volatile("mma.sync.aligned.m16n8k16.row.col.f32.f16.f16.f32 "
        "{%0,%1,%2,%3}, {%4,%5,%6,%7}, {%8,%9}, {%0,%1,%2,%3};"
        : "+f"(c[0]), "+f"(c[1]), "+f"(c[2]), "+f"(c[3])
        : "r"(a[0]), "r"(a[1]), "r"(a[2]), "r"(a[3]), "r"(b0), "r"(b1));
}
__device__ __forceinline__ uint32_t packh(__half a, __half b) {
    return (uint32_t)__half_as_ushort(a) | ((uint32_t)__half_as_ushort(b) << 16);
}
__device__ __forceinline__ uint2 cvt4(float4 v) {
    return make_uint2(packh(__float2half(v.x), __float2half(v.y)),
                      packh(__float2half(v.z), __float2half(v.w)));
}
// fast GELU: tanh-form with hardware MUFU.TANH
__device__ __forceinline__ float gelu_fast(float v) {
    float u = v * v;
    float p = 0.79788456080286536f * v * fmaf(0.044715f, u, 1.0f);
    float t;
    asm("tanh.approx.f32 %0, %1;" : "=f"(t) : "f"(p));
    return 0.5f * v * (1.0f + t);
}

// stage layouts (k-tile = 64, pitch 144 = 128+16)
#define FB_OFF 18432
#define FSZ    36864
#define FSMEM  (3 * FSZ)
#define IB_OFF 18432
#define ISZ    36864
#define ISMEM  (3 * ISZ)

// fused-prep grid ranges
#define PREP_SPLIT_BLKS 8192
#define FILLT_BLKS      512
#define TRW_BLKS        512
#define WC_BLKS         64
#define PREP_BLKS (PREP_SPLIT_BLKS + FILLT_BLKS + TRW_BLKS + WC_BLKS)

// ---------------------------------------------------------------------------
// Fused prep: one launch does x->fp16, basis table, w transpose, w_conv cvt
// ---------------------------------------------------------------------------
__global__ __launch_bounds__(256) void prep_all(const float* __restrict__ x,
                                                const float* __restrict__ w_spec,
                                                const float* __restrict__ w_conv) {
    __shared__ float2 tile[64][33];
    int bid = blockIdx.x;
    int t = threadIdx.x;

    if (bid < PREP_SPLIT_BLKS) {
        // ---- x fp32 -> fp16, 8 elements per thread ----
        int i = bid * 256 + t;
        float4 a  = ((const float4*)x)[2 * i];
        float4 b4 = ((const float4*)x)[2 * i + 1];
        uint2 lo = cvt4(a), hi = cvt4(b4);
        ((uint4*)g_xh)[i] = make_uint4(lo.x, lo.y, hi.x, hi.y);
        return;
    }
    bid -= PREP_SPLIT_BLKS;
    if (bid < FILLT_BLKS) {
        // ---- basis table, 8 halves per thread, direct cospif ----
        int idx = bid * 256 + t;
        int base = idx * 8;
        int j = base >> 13;
        int n0 = base & (NN - 1);
        int m = j & 63;
        int phase = (j >= MODES) ? 6144 : 0;   // sin = cos shifted
        uint32_t h[4];
#pragma unroll
        for (int q = 0; q < 4; q++) {
            int t0 = (m * (n0 + 2 * q) + phase) & (NN - 1);
            int t1 = (m * (n0 + 2 * q + 1) + phase) & (NN - 1);
            float c0 = cospif((float)t0 * (1.0f / 4096.0f));
            float c1 = cospif((float)t1 * (1.0f / 4096.0f));
            h[q] = packh(__float2half(c0), __float2half(c1));
        }
        *(uint4*)(g_Th + base) = make_uint4(h[0], h[1], h[2], h[3]);
        return;
    }
    bid -= FILLT_BLKS;
    if (bid < TRW_BLKS) {
        // ---- w_spec [i][o][m][2] -> g_wT [m][o][i][2] via smem tile ----
        int o = bid & 127;
        int i0 = (bid >> 7) * 32;
        const float4* src4 = (const float4*)w_spec;
#pragma unroll
        for (int q = 0; q < 4; q++) {
            int idx = t + q * 256;
            int m4 = idx & 31;
            int i  = idx >> 5;
            float4 v = src4[((size_t)(i0 + i) * 128 + o) * 32 + m4];
            tile[2 * m4][i]     = make_float2(v.x, v.y);
            tile[2 * m4 + 1][i] = make_float2(v.z, v.w);
        }
        __syncthreads();
        float4* dst4 = (float4*)g_wT;
#pragma unroll
        for (int q = 0; q < 4; q++) {
            int idx = t + q * 256;
            int il = idx & 15;
            int m  = idx >> 4;
            float2 a = tile[m][il * 2], b = tile[m][il * 2 + 1];
            dst4[((size_t)m * 128 + o) * 64 + (i0 >> 1) + il] = make_float4(a.x, a.y, b.x, b.y);
        }
        return;
    }
    bid -= TRW_BLKS;
    {
        // ---- w_conv fp32 -> fp16 ----
        int idx = bid * 256 + t;
        g_wc[idx] = __float2half(w_conv[idx]);
    }
}

// ---------------------------------------------------------------------------
// fwd compute: one 128x128x64 tile, single-pass fp16
// ---------------------------------------------------------------------------
__device__ __forceinline__ void compute_tile_f(float acc[2][8][4], uint32_t stg,
                                               int wm, int wn, int lane) {
    uint32_t n_off = (lane & 7) + ((lane >> 4) << 3);
    uint32_t kb = ((lane >> 3) & 1) * 16;
#pragma unroll
    for (int s16 = 0; s16 < 4; s16++) {
        uint32_t ah[2][4];
        uint32_t aaddr = stg + (uint32_t)(wm * 32 + (lane & 15)) * 144
                       + s16 * 32 + (lane >> 4) * 16;
        LDSM4(ah[0], aaddr);
        LDSM4(ah[1], aaddr + 16 * 144);
        uint32_t baddr = stg + FB_OFF + (uint32_t)(wn * 64 + n_off) * 144 + s16 * 32 + kb;
#pragma unroll
        for (int nb = 0; nb < 4; nb++) {
            uint32_t bh[4];
            LDSM4(bh, baddr + nb * 16 * 144);
#pragma unroll
            for (int half = 0; half < 2; half++) {
                int n = nb * 2 + half;
#pragma unroll
                for (int m = 0; m < 2; m++)
                    mma16816(acc[m][n], ah[m], bh[half * 2], bh[half * 2 + 1]);
            }
        }
    }
}

// inv compute: B via ldmatrix.trans on [k][n] layout (pitch 272)
__device__ __forceinline__ void compute_tile_i(float acc[2][8][4], uint32_t stg,
                                               int wm, int wn, int lane) {
#pragma unroll
    for (int s16 = 0; s16 < 4; s16++) {
        uint32_t ah[2][4];
        uint32_t aaddr = stg + (uint32_t)(wm * 32 + (lane & 15)) * 144
                       + s16 * 32 + (lane >> 4) * 16;
        LDSM4(ah[0], aaddr);
        LDSM4(ah[1], aaddr + 16 * 144);
        uint32_t baddr = stg + IB_OFF + (uint32_t)(s16 * 16 + (lane & 15)) * 272
                       + (uint32_t)(wn * 64) * 2 + (lane >> 4) * 16;
#pragma unroll
        for (int nb = 0; nb < 4; nb++) {
            uint32_t bh[4];
            LDSM4T(bh, baddr + nb * 32);
#pragma unroll
            for (int m = 0; m < 2; m++) {
                mma16816(acc[m][nb * 2],     ah[m], bh[0], bh[1]);
                mma16816(acc[m][nb * 2 + 1], ah[m], bh[2], bh[3]);
            }
        }
    }
}

// ---------------------------------------------------------------------------
// Forward GEMM: Pt[ks][b][j][i] = sum_k xh[b*128+i][k] * T[j][k]
// grid (BB, KSPLIT), 256 threads, 2 CTAs/SM; K-chunk 512 = 8 k64-tiles
// ---------------------------------------------------------------------------
__global__ __launch_bounds__(256, 2) void gemm_fwd_mma() {
    extern __shared__ char smem[];
    uint32_t sb = smem_u32(smem);
    int t = threadIdx.x, lane = t & 31, wid = t >> 5;
    int wm = wid & 3, wn = wid >> 2;
    int b = blockIdx.x, ks = blockIdx.y;
    int r0 = b * 128, kbase = ks * (NN / KSPLIT);
    const int NT = (NN / KSPLIT) / 64;   // 8

    float acc[2][8][4];
#pragma unroll
    for (int m = 0; m < 2; m++)
#pragma unroll
        for (int n = 0; n < 8; n++)
#pragma unroll
            for (int e = 0; e < 4; e++) acc[m][n][e] = 0.f;

#define FWD_ISSUE(T) do { \
    int _k0 = kbase + (T) * 64; \
    uint32_t _st = sb + ((T) % 3) * FSZ; \
    _Pragma("unroll") \
    for (int q = 0; q < 4; q++) { \
        int c = t + q * 256, row = c >> 3, u = c & 7; \
        CP16(_st + row * 144 + u * 16, g_xh + (size_t)(r0 + row) * NN + _k0 + u * 8); \
        CP16(_st + FB_OFF + row * 144 + u * 16, g_Th + (size_t)row * NN + _k0 + u * 8); \
    } \
    CPCOMMIT(); \
} while (0)

    FWD_ISSUE(0);
    FWD_ISSUE(1);
#pragma unroll
    for (int tile = 0; tile < NT; tile++) {
        if (tile + 1 < NT) { CPWAIT1(); } else { CPWAIT0(); }
        __syncthreads();
        compute_tile_f(acc, sb + (tile % 3) * FSZ, wm, wn, lane);
        if (tile + 2 < NT) FWD_ISSUE(tile + 2);
    }
    __syncthreads();

    // epilogue: transpose through SMEM -> g_Pt[ks][b][j][i]
    float* ftile = (float*)smem;   // [j][132]
#pragma unroll
    for (int m = 0; m < 2; m++) {
        int r1 = wm * 32 + m * 16 + (lane >> 2);
#pragma unroll
        for (int n = 0; n < 8; n++) {
            int j = wn * 64 + n * 8 + (lane & 3) * 2;
            ftile[j * 132 + r1]           = acc[m][n][0];
            ftile[(j + 1) * 132 + r1]     = acc[m][n][1];
            ftile[j * 132 + r1 + 8]       = acc[m][n][2];
            ftile[(j + 1) * 132 + r1 + 8] = acc[m][n][3];
        }
    }
    __syncthreads();
    float* P = g_Pt + ((size_t)(ks * BB + b)) * 128 * 128;
#pragma unroll
    for (int w = 0; w < 16; w++) {
        int idx4 = t + w * 256;
        int j = idx4 >> 5, i4 = idx4 & 31;
        *(float4*)(P + (size_t)j * 128 + i4 * 4) = *(const float4*)&ftile[j * 132 + i4 * 4];
    }
}

// ---------------------------------------------------------------------------
// Mode mix (folds split-K reduce) -> fp16 coefficients into g_Ah [b][o][k<128]
// ---------------------------------------------------------------------------
__global__ __launch_bounds__(256) void mode_mix() {
    int m = blockIdx.x, bg = blockIdx.y;
    int t = threadIdx.x;
    __shared__ float Fre[4][128], Fim[4][128];
#pragma unroll
    for (int q = 0; q < 2; q++) {
        int flat = t + q * 256;
        int bq = flat >> 7, i = flat & 127;
        int b = bg * 4 + bq;
        float sr = 0.f, si = 0.f;
#pragma unroll
        for (int ks = 0; ks < KSPLIT; ks++) {
            const float* Pb = g_Pt + ((size_t)(ks * BB + b)) * 128 * 128;
            sr += Pb[(size_t)m * 128 + i];
            si += Pb[(size_t)(64 + m) * 128 + i];
        }
        Fre[bq][i] = sr;
        Fim[bq][i] = -si;
    }
    __syncthreads();
    int o = t & 127, half = t >> 7;   // half handles batches half*2, half*2+1
    float aR[2] = {0.f, 0.f}, aI[2] = {0.f, 0.f};
    const float2* wrow = (const float2*)g_wT + (size_t)(m * CCH + o) * CCH;
#pragma unroll 8
    for (int i = 0; i < CCH; i++) {
        float2 w = wrow[i];
#pragma unroll
        for (int p = 0; p < 2; p++) {
            int bq = half * 2 + p;
            float fr = Fre[bq][i], fi = Fim[bq][i];
            aR[p] = fmaf(fr, w.x, fmaf(-fi, w.y, aR[p]));
            aI[p] = fmaf(fr, w.y, fmaf( fi, w.x, aI[p]));
        }
    }
    float sR = (m == 0) ? (1.0f / (float)NN) : (2.0f / (float)NN);
    float sI = (m == 0) ? 0.0f : (-2.0f / (float)NN);
#pragma unroll
    for (int p = 0; p < 2; p++) {
        int b = bg * 4 + half * 2 + p;
        size_t base = ((size_t)(b * 128 + o)) * 128;
        g_Ah[base + m]      = __float2half(aR[p] * sR);
        g_Ah[base + 64 + m] = __float2half(aI[p] * sI);
    }
}

// ---------------------------------------------------------------------------
// Inverse GEMM (fused iDFT + conv1x1 + bias + fast GELU)
// D[o][n] = sum_k A[o][k]*B[k][n], K=256. Two 128-wide n-tiles per CTA in one
// continuous 8-tile pipeline. grid (32 nt-pairs, 16 b)
// ---------------------------------------------------------------------------
__global__ __launch_bounds__(256, 2) void gemm_inv_mma(const float* __restrict__ b_conv,
                                                       float* __restrict__ out) {
    extern __shared__ char smem[];
    uint32_t sb = smem_u32(smem);
    int t = threadIdx.x, lane = t & 31, wid = t >> 5;
    int wm = wid & 3, wn = wid >> 2;
    int ntp = blockIdx.x, b = blockIdx.y;
    const int TT = 8;   // 2 n-tiles x 4 k-tiles

    const __half* Ahb = g_Ah + (size_t)b * 16384;

    float acc[2][8][4];
#pragma unroll
    for (int m = 0; m < 2; m++)
#pragma unroll
        for (int n = 0; n < 8; n++)
#pragma unroll
            for (int e = 0; e < 4; e++) acc[m][n][e] = 0.f;

#define INV_ISSUE(T) do { \
    int _n0 = (ntp * 2 + ((T) >> 2)) * 128; \
    int _k0 = ((T) & 3) * 64; \
    uint32_t _st = sb + ((T) % 3) * ISZ; \
    const __half* _Asrc = (_k0 < 128) ? (Ahb + _k0) : (g_wc + (_k0 - 128)); \
    _Pragma("unroll") \
    for (int q = 0; q < 4; q++) { \
        int c = t + q * 256, row = c >> 3, u = c & 7; \
        CP16(_st + row * 144 + u * 16, _Asrc + (size_t)row * 128 + u * 8); \
    } \
    _Pragma("unroll") \
    for (int q = 0; q < 4; q++) { \
        int c = t + q * 256, kr = c >> 4, cc = c & 15; \
        int _k = _k0 + kr; \
        const __half* src = (_k < 128) ? (g_Th + (size_t)_k * NN + _n0) \
                                       : (g_xh + (size_t)(b * 128 + _k - 128) * NN + _n0); \
        CP16(_st + IB_OFF + kr * 272 + cc * 16, src + cc * 8); \
    } \
    CPCOMMIT(); \
} while (0)

    INV_ISSUE(0);
    INV_ISSUE(1);
#pragma unroll
    for (int tt = 0; tt < TT; tt++) {
        if (tt + 1 < TT) { CPWAIT1(); } else { CPWAIT0(); }
        __syncthreads();
        compute_tile_i(acc, sb + (tt % 3) * ISZ, wm, wn, lane);
        if (tt + 2 < TT) INV_ISSUE(tt + 2);

        if ((tt & 3) == 3) {
            // epilogue for this n-tile (register-only; overlaps next prefetch)
            int n0 = (ntp * 2 + (tt >> 2)) * 128;
#pragma unroll
            for (int m = 0; m < 2; m++) {
                int o0 = wm * 32 + m * 16 + (lane >> 2);
                float bias0 = b_conv[o0];
                float bias1 = b_conv[o0 + 8];
#pragma unroll
                for (int n = 0; n < 8; n++) {
                    int ng = n0 + wn * 64 + n * 8 + (lane & 3) * 2;
                    float v0 = gelu_fast(acc[m][n][0] + bias0);
                    float v1 = gelu_fast(acc[m][n][1] + bias0);
                    float v2 = gelu_fast(acc[m][n][2] + bias1);
                    float v3 = gelu_fast(acc[m][n][3] + bias1);
                    *(float2*)(out + ((size_t)(b * 128 + o0)) * NN + ng)     = make_float2(v0, v1);
                    *(float2*)(out + ((size_t)(b * 128 + o0 + 8)) * NN + ng) = make_float2(v2, v3);
                }
            }
#pragma unroll
            for (int m = 0; m < 2; m++)
#pragma unroll
                for (int n = 0; n < 8; n++)
#pragma unroll
                    for (int e = 0; e < 4; e++) acc[m][n][e] = 0.f;
        }
    }
}

// ---------------------------------------------------------------------------
extern "C" void kernel_launch(void* const* d_in, const int* in_sizes, int n_in,
                              void* d_out, int out_size) {
    const float* x      = (const float*)d_in[0];
    const float* w_spec = (const float*)d_in[1];
    const float* w_conv = (const float*)d_in[2];
    const float* b_conv = (const float*)d_in[3];
    float* out = (float*)d_out;

    cudaFuncSetAttribute(gemm_fwd_mma, cudaFuncAttributeMaxDynamicSharedMemorySize, FSMEM);
    cudaFuncSetAttribute(gemm_inv_mma, cudaFuncAttributeMaxDynamicSharedMemorySize, ISMEM);

    prep_all    <<<PREP_BLKS, 256>>>(x, w_spec, w_conv);
    gemm_fwd_mma<<<dim3(BB, KSPLIT), 256, FSMEM>>>();
    mode_mix    <<<dim3(MODES, 4), 256>>>();
    gemm_inv_mma<<<dim3(NN / 256, BB), 256, ISMEM>>>(b_conv, out);
}